// round 16
// baseline (speedup 1.0000x reference)
#include <cuda_runtime.h>
#include <cuda_fp16.h>
#include <cstdint>

// Problem constants (fixed shapes for SparseLinear_40278203302401)
#define BATCH 32
#define NNODES 100000
#define MNODES 100000
#define NNZ_TOTAL 3200000
#define NTILES 3125            // N/32 == M/32

// Scratch: x transposed to (N, B) in fp16 (6.4 MB) and fp32 accumulator
// in (M, B) layout (12.8 MB). Both L2 resident.
__device__ __half g_xt_h[NNODES * BATCH];
__device__ float  g_yt[MNODES * BATCH];

__device__ __forceinline__ void red_add_v4(float* addr, float4 c) {
    asm volatile("red.global.add.v4.f32 [%0], {%1, %2, %3, %4};"
                 :: "l"(addr), "f"(c.x), "f"(c.y), "f"(c.z), "f"(c.w)
                 : "memory");
}

// -------------------------------------------------------------------------
// Kernel 1 (role-split):
//   blocks [0, PT_BLOCKS)        : transpose x -> xt fp16, 4 tiles/block
//   blocks [PT_BLOCKS, +Z_BLOCKS): zero yt (4 float4 stores per thread)
// Each CTA triggers programmatic launch completion after its stores, so
// k_edges (PDL secondary) can overlap its meta loads with prep's tail.
// -------------------------------------------------------------------------
#define PT_BLOCKS ((NTILES + 3) / 4)               // 782
#define YT_F4     (MNODES * BATCH / 4)             // 800000 float4s
#define Z_BLOCKS  ((YT_F4 + 1023) / 1024)          // 782

__global__ void __launch_bounds__(256)
k_prep(const float* __restrict__ x, __half* __restrict__ xt,
       float4* __restrict__ yt4) {
    if (blockIdx.x < PT_BLOCKS) {
        __shared__ float tile[4][32][33];
        const int t  = threadIdx.x;
        const int r  = t >> 3;        // 0..31
        const int c4 = t & 7;         // 0..7
        const int t0 = blockIdx.x * 4;
        const int nt = min(4, NTILES - t0);

        // batch all loads first (MLP = 4)
        float4 v[4];
        #pragma unroll
        for (int k = 0; k < 4; k++) {
            if (k < nt)
                v[k] = *(const float4*)&x[r * NNODES + (t0 + k) * 32 + c4 * 4];
        }
        #pragma unroll
        for (int k = 0; k < 4; k++) {
            if (k < nt) {
                tile[k][r][c4 * 4 + 0] = v[k].x;
                tile[k][r][c4 * 4 + 1] = v[k].y;
                tile[k][r][c4 * 4 + 2] = v[k].z;
                tile[k][r][c4 * 4 + 3] = v[k].w;
            }
        }
        __syncthreads();

        // r = n_local, c4 = batch-quad; 4 halves -> one 8B store per tile
        #pragma unroll
        for (int k = 0; k < 4; k++) {
            if (k < nt) {
                __half2 h0 = __float22half2_rn(
                    make_float2(tile[k][c4 * 4 + 0][r], tile[k][c4 * 4 + 1][r]));
                __half2 h1 = __float22half2_rn(
                    make_float2(tile[k][c4 * 4 + 2][r], tile[k][c4 * 4 + 3][r]));
                uint2 p;
                p.x = *reinterpret_cast<unsigned*>(&h0);
                p.y = *reinterpret_cast<unsigned*>(&h1);
                *(uint2*)&xt[((t0 + k) * 32 + r) * BATCH + c4 * 4] = p;
            }
        }
    } else {
        // ---- zero yt: 4 float4 stores per thread ----
        const int base = (blockIdx.x - PT_BLOCKS) * 1024 + threadIdx.x;
        const float4 z = make_float4(0.f, 0.f, 0.f, 0.f);
        #pragma unroll
        for (int k = 0; k < 4; k++) {
            const int idx = base + k * 256;
            if (idx < YT_F4) yt4[idx] = z;
        }
    }
#if __CUDA_ARCH__ >= 900
    cudaTriggerProgrammaticLaunchCompletion();
#endif
}

// -------------------------------------------------------------------------
// Kernel 2: edge scatter (PDL secondary). Loads its meta (independent of
// prep's outputs) BEFORE cudaGridDependencySynchronize(), overlapping the
// 38.4MB meta DRAM fetch with prep's tail. Then 8 lanes per edge: one 8B
// fp16 gather, fp32 math, red.v4.f32 scatter.
// -------------------------------------------------------------------------
__global__ void __launch_bounds__(256)
k_edges(const int* __restrict__ src, const int* __restrict__ dst,
        const float* __restrict__ val,
        const __half* __restrict__ xt, float* yt) {
    const int warp_id = (blockIdx.x * blockDim.x + threadIdx.x) >> 5;
    const int lane = threadIdx.x & 31;
    const int e0 = warp_id * 32;

    int   s = 0, d = 0;
    float v = 0.0f;
    if (e0 < NNZ_TOTAL) {
        s = src[e0 + lane];
        d = dst[e0 + lane];
        v = val[e0 + lane];
    }

#if __CUDA_ARCH__ >= 900
    cudaGridDependencySynchronize();   // wait for prep's xt + yt-zero
#endif
    if (e0 >= NNZ_TOTAL) return;

    const int g   = lane >> 3;   // edge-group 0..3
    const int sub = lane & 7;    // batch-quad 0..7

    #pragma unroll
    for (int j = 0; j < 8; j++) {
        const int srcLane = j * 4 + g;
        const int   sj = __shfl_sync(0xffffffffu, s, srcLane);
        const int   dj = __shfl_sync(0xffffffffu, d, srcLane);
        const float vj = __shfl_sync(0xffffffffu, v, srcLane);

        const int2 raw = __ldg((const int2*)&xt[sj * BATCH + sub * 4]);
        const __half2 a0 = *reinterpret_cast<const __half2*>(&raw.x);
        const __half2 a1 = *reinterpret_cast<const __half2*>(&raw.y);
        const float2 f0 = __half22float2(a0);
        const float2 f1 = __half22float2(a1);

        float4 c;
        c.x = vj * f0.x;
        c.y = vj * f0.y;
        c.z = vj * f1.x;
        c.w = vj * f1.y;
        red_add_v4(&yt[dj * BATCH + sub * 4], c);
    }
    // implicit trigger at exit for the next PDL stage
}

// -------------------------------------------------------------------------
// Kernel 3 (PDL secondary): transpose y_t (M, 32) -> out (B, M) + bias.
// Loads bias (independent) before the grid sync; yt loads after.
// -------------------------------------------------------------------------
#define W_BLOCKS ((NTILES + 3) / 4)   // 782

__global__ void __launch_bounds__(256)
k_write_out(const float* __restrict__ yt, const float* __restrict__ bias,
            float* __restrict__ out) {
    __shared__ float tile[4][32][33];
    const int t  = threadIdx.x;
    const int r  = t >> 3;        // 0..31
    const int c4 = t & 7;         // 0..7
    const int t0 = blockIdx.x * 4;
    const int nt = min(4, NTILES - t0);

    // independent preamble: bias loads
    float4 bb[4];
    #pragma unroll
    for (int k = 0; k < 4; k++) {
        if (k < nt) bb[k] = *(const float4*)&bias[(t0 + k) * 32 + c4 * 4];
    }

#if __CUDA_ARCH__ >= 900
    cudaGridDependencySynchronize();   // wait for all edge REDs
#endif

    float4 v[4];
    #pragma unroll
    for (int k = 0; k < 4; k++) {
        if (k < nt)
            v[k] = *(const float4*)&yt[((t0 + k) * 32 + r) * BATCH + c4 * 4];
    }
    #pragma unroll
    for (int k = 0; k < 4; k++) {
        if (k < nt) {
            tile[k][c4 * 4 + 0][r] = v[k].x;   // tile[k][b][m_local]
            tile[k][c4 * 4 + 1][r] = v[k].y;
            tile[k][c4 * 4 + 2][r] = v[k].z;
            tile[k][c4 * 4 + 3][r] = v[k].w;
        }
    }
    __syncthreads();

    #pragma unroll
    for (int k = 0; k < 4; k++) {
        if (k < nt) {
            const int m = (t0 + k) * 32;
            float4 o;
            o.x = tile[k][r][c4 * 4 + 0] + bb[k].x;
            o.y = tile[k][r][c4 * 4 + 1] + bb[k].y;
            o.z = tile[k][r][c4 * 4 + 2] + bb[k].z;
            o.w = tile[k][r][c4 * 4 + 3] + bb[k].w;
            *(float4*)&out[r * MNODES + m + c4 * 4] = o;
        }
    }
}

// -------------------------------------------------------------------------
// Launch. PDL: k_edges and k_write_out use ProgrammaticStreamSerialization
// so each overlaps its independent preamble with the previous kernel's tail.
// -------------------------------------------------------------------------
extern "C" void kernel_launch(void* const* d_in, const int* in_sizes, int n_in,
                              void* d_out, int out_size) {
    const float* x      = (const float*)d_in[0];
    const int*   indices= (const int*)d_in[1];
    const float* values = (const float*)d_in[2];
    const float* bias   = (const float*)d_in[3];
    float* out = (float*)d_out;

    const int* src = indices;              // row 0
    const int* dst = indices + NNZ_TOTAL;  // row 1

    __half* xt; cudaGetSymbolAddress((void**)&xt, g_xt_h);
    float*  yt; cudaGetSymbolAddress((void**)&yt, g_yt);

    // 1. fused: transpose x -> fp16 xt + zero yt
    k_prep<<<PT_BLOCKS + Z_BLOCKS, 256>>>(x, xt, (float4*)yt);

    cudaLaunchAttribute pdl[1];
    pdl[0].id = cudaLaunchAttributeProgrammaticStreamSerialization;
    pdl[0].val.programmaticStreamSerializationAllowed = 1;

    // 2. edge scatter (PDL: overlap meta loads with prep tail)
    {
        const int n_warps = NNZ_TOTAL / 32;
        cudaLaunchConfig_t cfg = {};
        cfg.gridDim  = dim3((n_warps + 7) / 8);
        cfg.blockDim = dim3(256);
        cfg.attrs = pdl;
        cfg.numAttrs = 1;
        cudaLaunchKernelEx(&cfg, k_edges, src, dst, values,
                           (const __half*)xt, yt);
    }

    // 3. transposed output + bias (PDL: overlap launch + bias loads)
    {
        cudaLaunchConfig_t cfg = {};
        cfg.gridDim  = dim3(W_BLOCKS);
        cfg.blockDim = dim3(256);
        cfg.attrs = pdl;
        cfg.numAttrs = 1;
        cudaLaunchKernelEx(&cfg, k_write_out, (const float*)yt, bias, out);
    }
}